// round 1
// baseline (speedup 1.0000x reference)
#include <cuda_runtime.h>

#define BATCH 16
#define CH    512
#define SEQ   1024
#define NH    8
#define DK    64
#define N3    1536          // 3*CH
#define SCALE 0.125f        // 1/sqrt(64)

// ---------------- scratch (device globals: allocation-free) ----------------
__device__ float g_Q[BATCH * NH * SEQ * DK];   // [b,h,s,d]
__device__ float g_K[BATCH * NH * SEQ * DK];
__device__ float g_V[BATCH * NH * SEQ * DK];
__device__ float g_O[BATCH * SEQ * CH];        // [b,s,c] attention output

// ======================= kernel 1: QKV GEMM + scatter ======================
// C[m,n] = sum_k xr[m,k]*w[k,n] + bias[n],  m=(b,s), xr[m,k]=x[b,k,s]
// M=16384, N=1536, K=512. Tile 128x64x16, thread tile 8x4, 256 threads.
__global__ __launch_bounds__(256) void qkv_kernel(const float* __restrict__ x,
                                                  const float* __restrict__ w,
                                                  const float* __restrict__ bias) {
    __shared__ float As[16 * 128];   // [k][m]
    __shared__ float Bs[16 * 64];    // [k][n]

    const int m0 = blockIdx.x * 128;
    const int n0 = blockIdx.y * 64;
    const int b  = m0 >> 10;
    const int s0 = m0 & 1023;
    const int tid = threadIdx.x;
    const int tx = tid & 15, ty = tid >> 4;

    const float* xb = x + b * CH * SEQ + s0;   // + k*SEQ + m
    const float* wb = w + n0;                  // + k*N3 + n

    float acc[8][4];
#pragma unroll
    for (int r = 0; r < 8; r++)
#pragma unroll
        for (int c = 0; c < 4; c++) acc[r][c] = 0.f;

    for (int k0 = 0; k0 < CH; k0 += 16) {
#pragma unroll
        for (int t = 0; t < 2; ++t) {          // A tile: 16x128 floats
            int f = tid * 4 + t * 1024;
            int kk = f >> 7, mm = f & 127;
            *(float4*)&As[kk * 128 + mm] =
                *(const float4*)&xb[(k0 + kk) * SEQ + mm];
        }
        {                                      // B tile: 16x64 floats
            int f = tid * 4;
            int kk = f >> 6, nn = f & 63;
            *(float4*)&Bs[kk * 64 + nn] =
                *(const float4*)&wb[(k0 + kk) * N3 + nn];
        }
        __syncthreads();
#pragma unroll
        for (int kk = 0; kk < 16; ++kk) {
            float a[8], bv[4];
            *(float4*)&a[0] = *(float4*)&As[kk * 128 + ty * 8];
            *(float4*)&a[4] = *(float4*)&As[kk * 128 + ty * 8 + 4];
            *(float4*)&bv[0] = *(float4*)&Bs[kk * 64 + tx * 4];
#pragma unroll
            for (int r = 0; r < 8; r++)
#pragma unroll
                for (int c = 0; c < 4; c++) acc[r][c] += a[r] * bv[c];
        }
        __syncthreads();
    }

    // scatter: n = h*192 + r0 (+ local). n-tile (64 wide) never spans q/k/v.
    const int h  = n0 / 192;
    const int r0 = n0 % 192;                   // 0, 64 or 128 exactly
    float* dst = (r0 < 64) ? g_Q : (r0 < 128 ? g_K : g_V);
    const float4 b4 = *(const float4*)&bias[n0 + tx * 4];
    const int bh = b * NH + h;
#pragma unroll
    for (int r = 0; r < 8; r++) {
        int s = s0 + ty * 8 + r;
        float4 v = make_float4(acc[r][0] + b4.x, acc[r][1] + b4.y,
                               acc[r][2] + b4.z, acc[r][3] + b4.w);
        *(float4*)&dst[(bh * SEQ + s) * DK + tx * 4] = v;
    }
}

// ==================== kernel 2: flash attention (fp32) =====================
// CTA = (query tile of 64, (b,h)). j-tiles of 64, online softmax.
#define PAD 68   // smem row stride (floats): conflict-free, float4-aligned
__global__ __launch_bounds__(256) void attn_kernel() {
    extern __shared__ float smem2[];
    float* Qs = smem2;                 // 64*PAD
    float* Ks = Qs + 64 * PAD;
    float* Vs = Ks + 64 * PAD;
    float* Ps = Vs + 64 * PAD;

    const int i0 = blockIdx.x * 64;
    const int bh = blockIdx.y;
    const int tid = threadIdx.x;
    const int tx = tid & 15, ty = tid >> 4;

    const float* Qg = g_Q + (bh * SEQ + i0) * DK;
#pragma unroll
    for (int t = 0; t < 4; ++t) {
        int f = tid * 4 + t * 1024;
        int ii = f >> 6, dd = f & 63;
        *(float4*)&Qs[ii * PAD + dd] = *(const float4*)&Qg[ii * 64 + dd];
    }

    float o[4][4];
    float m[4], l[4];
#pragma unroll
    for (int r = 0; r < 4; r++) {
        m[r] = -1e30f; l[r] = 0.f;
#pragma unroll
        for (int c = 0; c < 4; c++) o[r][c] = 0.f;
    }

    for (int jt = 0; jt < 16; ++jt) {
        __syncthreads();   // protect Ks/Vs/Ps from previous iteration readers
        const float* Kg = g_K + (bh * SEQ + jt * 64) * DK;
        const float* Vg = g_V + (bh * SEQ + jt * 64) * DK;
#pragma unroll
        for (int t = 0; t < 4; ++t) {
            int f = tid * 4 + t * 1024;
            int ii = f >> 6, dd = f & 63;
            *(float4*)&Ks[ii * PAD + dd] = *(const float4*)&Kg[ii * 64 + dd];
            *(float4*)&Vs[ii * PAD + dd] = *(const float4*)&Vg[ii * 64 + dd];
        }
        __syncthreads();

        // S = scale * Q K^T   (64x64, thread tile 4x4, contraction d=64)
        float s[4][4];
#pragma unroll
        for (int r = 0; r < 4; r++)
#pragma unroll
            for (int c = 0; c < 4; c++) s[r][c] = 0.f;

#pragma unroll
        for (int d = 0; d < 64; d += 4) {
            float4 aq[4], bk[4];
#pragma unroll
            for (int r = 0; r < 4; r++)
                aq[r] = *(float4*)&Qs[(ty * 4 + r) * PAD + d];
#pragma unroll
            for (int c = 0; c < 4; c++)
                bk[c] = *(float4*)&Ks[(tx * 4 + c) * PAD + d];
#pragma unroll
            for (int r = 0; r < 4; r++)
#pragma unroll
                for (int c = 0; c < 4; c++)
                    s[r][c] += aq[r].x * bk[c].x + aq[r].y * bk[c].y +
                               aq[r].z * bk[c].z + aq[r].w * bk[c].w;
        }
#pragma unroll
        for (int r = 0; r < 4; r++)
#pragma unroll
            for (int c = 0; c < 4; c++) s[r][c] *= SCALE;

        // online softmax; each row lives in one 16-lane group (lanes share ty)
#pragma unroll
        for (int r = 0; r < 4; r++) {
            float mx = fmaxf(fmaxf(s[r][0], s[r][1]), fmaxf(s[r][2], s[r][3]));
#pragma unroll
            for (int off = 8; off >= 1; off >>= 1)
                mx = fmaxf(mx, __shfl_xor_sync(0xffffffffu, mx, off));
            float mn = fmaxf(m[r], mx);
            float corr = __expf(m[r] - mn);
            float rs = 0.f;
#pragma unroll
            for (int c = 0; c < 4; c++) {
                s[r][c] = __expf(s[r][c] - mn);
                rs += s[r][c];
            }
#pragma unroll
            for (int off = 8; off >= 1; off >>= 1)
                rs += __shfl_xor_sync(0xffffffffu, rs, off);
            l[r] = l[r] * corr + rs;
            m[r] = mn;
#pragma unroll
            for (int c = 0; c < 4; c++) o[r][c] *= corr;
        }

        // stage P through smem for the PV contraction
#pragma unroll
        for (int r = 0; r < 4; r++)
            *(float4*)&Ps[(ty * 4 + r) * PAD + tx * 4] =
                make_float4(s[r][0], s[r][1], s[r][2], s[r][3]);
        __syncthreads();

        // O += P V   (contraction over j=64)
#pragma unroll
        for (int j = 0; j < 64; j += 4) {
            float4 p4[4], v4[4];
#pragma unroll
            for (int r = 0; r < 4; r++)
                p4[r] = *(float4*)&Ps[(ty * 4 + r) * PAD + j];
#pragma unroll
            for (int jj = 0; jj < 4; jj++)
                v4[jj] = *(float4*)&Vs[(j + jj) * PAD + tx * 4];
#pragma unroll
            for (int r = 0; r < 4; r++) {
                o[r][0] += p4[r].x * v4[0].x + p4[r].y * v4[1].x +
                           p4[r].z * v4[2].x + p4[r].w * v4[3].x;
                o[r][1] += p4[r].x * v4[0].y + p4[r].y * v4[1].y +
                           p4[r].z * v4[2].y + p4[r].w * v4[3].y;
                o[r][2] += p4[r].x * v4[0].z + p4[r].y * v4[1].z +
                           p4[r].z * v4[2].z + p4[r].w * v4[3].z;
                o[r][3] += p4[r].x * v4[0].w + p4[r].y * v4[1].w +
                           p4[r].z * v4[2].w + p4[r].w * v4[3].w;
            }
        }
    }

    // epilogue: normalize and write O[b, s, h*64 + d]
    const int b = bh >> 3, h = bh & 7;
#pragma unroll
    for (int r = 0; r < 4; r++) {
        float inv = 1.0f / l[r];
        float4 v = make_float4(o[r][0] * inv, o[r][1] * inv,
                               o[r][2] * inv, o[r][3] * inv);
        *(float4*)&g_O[(b * SEQ + i0 + ty * 4 + r) * CH + h * DK + tx * 4] = v;
    }
}

// ============== kernel 3: proj GEMM + bias + residual + transpose ==========
// out[b,c,s] = sum_k O[b,s,k]*wp[k,c] + bp[c] + x[b,c,s]
__global__ __launch_bounds__(256) void proj_kernel(const float* __restrict__ wp,
                                                   const float* __restrict__ bp,
                                                   const float* __restrict__ x,
                                                   float* __restrict__ out) {
    __shared__ float As[16 * 132];   // [k][m], padded stride 132
    __shared__ float Bs[16 * 64];

    const int m0 = blockIdx.x * 128;
    const int n0 = blockIdx.y * 64;
    const int b  = m0 >> 10;
    const int s0 = m0 & 1023;
    const int tid = threadIdx.x;
    const int tx = tid & 15, ty = tid >> 4;

    const float* Ob = g_O + (b * SEQ + s0) * CH;   // + m*CH + k

    float acc[8][4];
#pragma unroll
    for (int r = 0; r < 8; r++)
#pragma unroll
        for (int c = 0; c < 4; c++) acc[r][c] = 0.f;

    for (int k0 = 0; k0 < CH; k0 += 16) {
#pragma unroll
        for (int t = 0; t < 2; ++t) {          // A tile 128x16, transpose to smem
            int f = tid * 4 + t * 1024;
            int mm = f >> 4, kk = f & 15;
            float4 v = *(const float4*)&Ob[mm * CH + k0 + kk];
            As[(kk + 0) * 132 + mm] = v.x;
            As[(kk + 1) * 132 + mm] = v.y;
            As[(kk + 2) * 132 + mm] = v.z;
            As[(kk + 3) * 132 + mm] = v.w;
        }
        {
            int f = tid * 4;
            int kk = f >> 6, nn = f & 63;
            *(float4*)&Bs[kk * 64 + nn] =
                *(const float4*)&wp[(k0 + kk) * CH + n0 + nn];
        }
        __syncthreads();
#pragma unroll
        for (int kk = 0; kk < 16; ++kk) {
            float a[8], bv[4];
            *(float4*)&a[0] = *(float4*)&As[kk * 132 + ty * 8];
            *(float4*)&a[4] = *(float4*)&As[kk * 132 + ty * 8 + 4];
            *(float4*)&bv[0] = *(float4*)&Bs[kk * 64 + tx * 4];
#pragma unroll
            for (int r = 0; r < 8; r++)
#pragma unroll
                for (int c = 0; c < 4; c++) acc[r][c] += a[r] * bv[c];
        }
        __syncthreads();
    }

    // epilogue: out[b,c,s] with residual; s contiguous per column -> float4
#pragma unroll
    for (int q = 0; q < 4; q++) {
        int c = n0 + tx * 4 + q;
        float bpv = bp[c];
        int base = b * CH * SEQ + c * SEQ + s0 + ty * 8;
        float4 x0 = *(const float4*)&x[base];
        float4 x1 = *(const float4*)&x[base + 4];
        float4 o0 = make_float4(acc[0][q] + bpv + x0.x, acc[1][q] + bpv + x0.y,
                                acc[2][q] + bpv + x0.z, acc[3][q] + bpv + x0.w);
        float4 o1 = make_float4(acc[4][q] + bpv + x1.x, acc[5][q] + bpv + x1.y,
                                acc[6][q] + bpv + x1.z, acc[7][q] + bpv + x1.w);
        *(float4*)&out[base]     = o0;
        *(float4*)&out[base + 4] = o1;
    }
}

// ================================ launch ==================================
extern "C" void kernel_launch(void* const* d_in, const int* in_sizes, int n_in,
                              void* d_out, int out_size) {
    const float* x      = (const float*)d_in[0];
    const float* w_qkv  = (const float*)d_in[1];
    const float* b_qkv  = (const float*)d_in[2];
    const float* w_proj = (const float*)d_in[3];
    const float* b_proj = (const float*)d_in[4];
    float* out = (float*)d_out;

    const int smem2 = 4 * 64 * PAD * sizeof(float);   // 69632 B
    cudaFuncSetAttribute(attn_kernel,
                         cudaFuncAttributeMaxDynamicSharedMemorySize, smem2);

    qkv_kernel<<<dim3(BATCH * SEQ / 128, N3 / 64), 256>>>(x, w_qkv, b_qkv);
    attn_kernel<<<dim3(SEQ / 64, BATCH * NH), 256, smem2>>>();
    proj_kernel<<<dim3(BATCH * SEQ / 128, CH / 64), 256>>>(w_proj, b_proj, x, out);
}

// round 2
// speedup vs baseline: 3.2836x; 3.2836x over previous
#include <cuda_runtime.h>

#define BATCH 16
#define CH    512
#define SEQ   1024
#define NH    8
#define DK    64
#define N3    1536
#define SCALE 0.125f

// ---------------- scratch (device globals: allocation-free) ----------------
__device__ float g_Q[BATCH * NH * SEQ * DK];   // [b,h,s,d] (tf32-rounded)
__device__ float g_K[BATCH * NH * SEQ * DK];
__device__ float g_V[BATCH * NH * SEQ * DK];
__device__ float g_O[BATCH * SEQ * CH];        // [b,s,c] fp32

// ------------------------------- helpers ----------------------------------
__device__ __forceinline__ unsigned f2tf(float f) {
    unsigned u;
    asm("cvt.rna.tf32.f32 %0, %1;" : "=r"(u) : "f"(f));
    return u;
}

__device__ __forceinline__ void mma8(float* d, const unsigned* a,
                                     const unsigned* b, const float* c) {
    asm volatile(
        "mma.sync.aligned.m16n8k8.row.col.f32.tf32.tf32.f32 "
        "{%0,%1,%2,%3}, {%4,%5,%6,%7}, {%8,%9}, {%10,%11,%12,%13};"
        : "=f"(d[0]), "=f"(d[1]), "=f"(d[2]), "=f"(d[3])
        : "r"(a[0]), "r"(a[1]), "r"(a[2]), "r"(a[3]),
          "r"(b[0]), "r"(b[1]),
          "f"(c[0]), "f"(c[1]), "f"(c[2]), "f"(c[3]));
}

// ======================= kernel 1: QKV GEMM + scatter ======================
// C[m,n] = sum_k x[b,k,s]*w[k,n] + bias[n].  M=16384, N=1536, K=512.
// CTA 128x128, k-tile 32, 8 warps of 32x64 (m16n8k8 tiles 2x8).
#define ASTR 136   // [k][m] smem stride: frag bank = 8*tx+g, conflict-free
__global__ __launch_bounds__(256) void qkv_kernel(const float* __restrict__ x,
                                                  const float* __restrict__ w,
                                                  const float* __restrict__ bias) {
    __shared__ unsigned As[32 * ASTR];   // [k][m]
    __shared__ unsigned Bs[32 * ASTR];   // [k][n]

    const int m0 = blockIdx.x * 128, n0 = blockIdx.y * 128;
    const int b  = m0 >> 10, s0 = m0 & 1023;
    const int tid = threadIdx.x, lane = tid & 31, wid = tid >> 5;
    const int g = lane >> 2, tx = lane & 3;
    const int wm = (wid & 3) * 32, wn = (wid >> 2) * 64;

    const float* xb = x + b * CH * SEQ + s0;   // + k*SEQ + m
    const float* wb = w + n0;                  // + k*N3 + n

    float acc[2][8][4];
#pragma unroll
    for (int mt = 0; mt < 2; mt++)
#pragma unroll
        for (int nt = 0; nt < 8; nt++)
#pragma unroll
            for (int i = 0; i < 4; i++) acc[mt][nt][i] = 0.f;

    for (int k0 = 0; k0 < CH; k0 += 32) {
#pragma unroll
        for (int t = 0; t < 4; t++) {
            int f = tid * 4 + t * 1024;
            int kk = f >> 7, mm = f & 127;
            float4 va = *(const float4*)&xb[(k0 + kk) * SEQ + mm];
            uint4 ua = make_uint4(f2tf(va.x), f2tf(va.y), f2tf(va.z), f2tf(va.w));
            *(uint4*)&As[kk * ASTR + mm] = ua;
            float4 vb = *(const float4*)&wb[(k0 + kk) * N3 + mm];
            uint4 ub = make_uint4(f2tf(vb.x), f2tf(vb.y), f2tf(vb.z), f2tf(vb.w));
            *(uint4*)&Bs[kk * ASTR + mm] = ub;
        }
        __syncthreads();
#pragma unroll
        for (int ks = 0; ks < 4; ks++) {
            const int kb = ks * 8;
            unsigned af[2][4];
#pragma unroll
            for (int mt = 0; mt < 2; mt++) {
                int mb = wm + mt * 16 + g;
                af[mt][0] = As[(kb + tx) * ASTR + mb];
                af[mt][1] = As[(kb + tx) * ASTR + mb + 8];
                af[mt][2] = As[(kb + tx + 4) * ASTR + mb];
                af[mt][3] = As[(kb + tx + 4) * ASTR + mb + 8];
            }
#pragma unroll
            for (int nt = 0; nt < 8; nt++) {
                unsigned bf[2];
                int nb = wn + nt * 8 + g;
                bf[0] = Bs[(kb + tx) * ASTR + nb];
                bf[1] = Bs[(kb + tx + 4) * ASTR + nb];
                mma8(acc[0][nt], af[0], bf, acc[0][nt]);
                mma8(acc[1][nt], af[1], bf, acc[1][nt]);
            }
        }
        __syncthreads();
    }

    // scatter epilogue: n -> (h, q/k/v segment, d). 2-col pairs never straddle.
#pragma unroll
    for (int nt = 0; nt < 8; nt++) {
        int n = n0 + wn + nt * 8 + 2 * tx;
        int h = n / 192, r = n - h * 192;
        float* dst; int d;
        if (r < 64)       { dst = g_Q; d = r; }
        else if (r < 128) { dst = g_K; d = r - 64; }
        else              { dst = g_V; d = r - 128; }
        float bv0 = bias[n], bv1 = bias[n + 1];
        int rowbase = (b * NH + h) * SEQ;
#pragma unroll
        for (int mt = 0; mt < 2; mt++) {
            int s = s0 + wm + mt * 16 + g;
            float2 lo = make_float2(__uint_as_float(f2tf(acc[mt][nt][0] + bv0)),
                                    __uint_as_float(f2tf(acc[mt][nt][1] + bv1)));
            *(float2*)&dst[(rowbase + s) * DK + d] = lo;
            float2 hi = make_float2(__uint_as_float(f2tf(acc[mt][nt][2] + bv0)),
                                    __uint_as_float(f2tf(acc[mt][nt][3] + bv1)));
            *(float2*)&dst[(rowbase + s + 8) * DK + d] = hi;
        }
    }
}

// ==================== kernel 2: flash attention (tf32 mma) =================
// CTA = 128 query rows x (b,h). 8 warps, each owns m16 rows. j-tiles of 64.
#define KSTR 72   // K/V smem [j][d]: frag bank = 8*g+tx (QK) / 8*tx+g (PV)
#define PSTR 76   // P smem [m][j]: A-frag bank = 12*g+tx, conflict-free
__global__ __launch_bounds__(256) void attn_kernel() {
    extern __shared__ float sm[];
    float* Ks = sm;                   // 64*KSTR
    float* Vs = Ks + 64 * KSTR;       // 64*KSTR
    float* Ps = Vs + 64 * KSTR;       // 128*PSTR

    const int i0 = blockIdx.x * 128;
    const int bh = blockIdx.y;
    const int tid = threadIdx.x, lane = tid & 31, wid = tid >> 5;
    const int g = lane >> 2, tx = lane & 3;

    // Q fragments in registers, scale folded in (8 k-steps of d)
    const float* Qg = g_Q + (bh * SEQ + i0 + wid * 16) * DK;
    unsigned qa[8][4];
#pragma unroll
    for (int ks = 0; ks < 8; ks++) {
        qa[ks][0] = f2tf(Qg[g * DK + ks * 8 + tx] * SCALE);
        qa[ks][1] = f2tf(Qg[(g + 8) * DK + ks * 8 + tx] * SCALE);
        qa[ks][2] = f2tf(Qg[g * DK + ks * 8 + tx + 4] * SCALE);
        qa[ks][3] = f2tf(Qg[(g + 8) * DK + ks * 8 + tx + 4] * SCALE);
    }

    float oacc[8][4];
#pragma unroll
    for (int nt = 0; nt < 8; nt++)
#pragma unroll
        for (int i = 0; i < 4; i++) oacc[nt][i] = 0.f;
    float m_lo = -1e30f, m_hi = -1e30f, l_lo = 0.f, l_hi = 0.f;

    const float* Kg0 = g_K + bh * SEQ * DK;
    const float* Vg0 = g_V + bh * SEQ * DK;

    for (int jt = 0; jt < 16; jt++) {
        __syncthreads();
        const float* Kg = Kg0 + jt * 64 * DK;
        const float* Vg = Vg0 + jt * 64 * DK;
#pragma unroll
        for (int t = 0; t < 4; t++) {
            int f = tid * 4 + t * 1024;
            int jj = f >> 6, dd = f & 63;
            *(float4*)&Ks[jj * KSTR + dd] = *(const float4*)&Kg[jj * DK + dd];
            *(float4*)&Vs[jj * KSTR + dd] = *(const float4*)&Vg[jj * DK + dd];
        }
        __syncthreads();

        // S = (scale*Q) K^T : 16x64, contraction d=64
        float sacc[8][4];
#pragma unroll
        for (int nt = 0; nt < 8; nt++)
#pragma unroll
            for (int i = 0; i < 4; i++) sacc[nt][i] = 0.f;
#pragma unroll
        for (int ks = 0; ks < 8; ks++) {
#pragma unroll
            for (int nt = 0; nt < 8; nt++) {
                unsigned bf[2];
                bf[0] = __float_as_uint(Ks[(nt * 8 + g) * KSTR + ks * 8 + tx]);
                bf[1] = __float_as_uint(Ks[(nt * 8 + g) * KSTR + ks * 8 + tx + 4]);
                mma8(sacc[nt], qa[ks], bf, sacc[nt]);
            }
        }

        // online softmax (rows g and g+8; row group = 4 lanes -> shfl 1,2)
        float mx_lo = -1e30f, mx_hi = -1e30f;
#pragma unroll
        for (int nt = 0; nt < 8; nt++) {
            mx_lo = fmaxf(mx_lo, fmaxf(sacc[nt][0], sacc[nt][1]));
            mx_hi = fmaxf(mx_hi, fmaxf(sacc[nt][2], sacc[nt][3]));
        }
#pragma unroll
        for (int off = 1; off <= 2; off <<= 1) {
            mx_lo = fmaxf(mx_lo, __shfl_xor_sync(0xffffffffu, mx_lo, off));
            mx_hi = fmaxf(mx_hi, __shfl_xor_sync(0xffffffffu, mx_hi, off));
        }
        float mn_lo = fmaxf(m_lo, mx_lo), mn_hi = fmaxf(m_hi, mx_hi);
        float corr_lo = __expf(m_lo - mn_lo), corr_hi = __expf(m_hi - mn_hi);
        float rs_lo = 0.f, rs_hi = 0.f;
        int prow = (wid * 16 + g) * PSTR;
#pragma unroll
        for (int nt = 0; nt < 8; nt++) {
            float p0 = __uint_as_float(f2tf(__expf(sacc[nt][0] - mn_lo)));
            float p1 = __uint_as_float(f2tf(__expf(sacc[nt][1] - mn_lo)));
            float p2 = __uint_as_float(f2tf(__expf(sacc[nt][2] - mn_hi)));
            float p3 = __uint_as_float(f2tf(__expf(sacc[nt][3] - mn_hi)));
            rs_lo += p0 + p1;
            rs_hi += p2 + p3;
            *(float2*)&Ps[prow + nt * 8 + 2 * tx] = make_float2(p0, p1);
            *(float2*)&Ps[prow + 8 * PSTR + nt * 8 + 2 * tx] = make_float2(p2, p3);
        }
#pragma unroll
        for (int off = 1; off <= 2; off <<= 1) {
            rs_lo += __shfl_xor_sync(0xffffffffu, rs_lo, off);
            rs_hi += __shfl_xor_sync(0xffffffffu, rs_hi, off);
        }
        l_lo = l_lo * corr_lo + rs_lo;  m_lo = mn_lo;
        l_hi = l_hi * corr_hi + rs_hi;  m_hi = mn_hi;
#pragma unroll
        for (int nt = 0; nt < 8; nt++) {
            oacc[nt][0] *= corr_lo; oacc[nt][1] *= corr_lo;
            oacc[nt][2] *= corr_hi; oacc[nt][3] *= corr_hi;
        }
        __syncwarp();

        // O += P V : contraction over j=64
#pragma unroll
        for (int ks = 0; ks < 8; ks++) {
            unsigned pa[4];
            pa[0] = __float_as_uint(Ps[prow + ks * 8 + tx]);
            pa[1] = __float_as_uint(Ps[prow + 8 * PSTR + ks * 8 + tx]);
            pa[2] = __float_as_uint(Ps[prow + ks * 8 + tx + 4]);
            pa[3] = __float_as_uint(Ps[prow + 8 * PSTR + ks * 8 + tx + 4]);
#pragma unroll
            for (int nt = 0; nt < 8; nt++) {
                unsigned bf[2];
                bf[0] = __float_as_uint(Vs[(ks * 8 + tx) * KSTR + nt * 8 + g]);
                bf[1] = __float_as_uint(Vs[(ks * 8 + tx + 4) * KSTR + nt * 8 + g]);
                mma8(oacc[nt], pa, bf, oacc[nt]);
            }
        }
    }

    // epilogue: O[b, s, h*64+d]
    float inv_lo = 1.f / l_lo, inv_hi = 1.f / l_hi;
    const int b = bh >> 3, h = bh & 7;
    const int srow = i0 + wid * 16 + g;
#pragma unroll
    for (int nt = 0; nt < 8; nt++) {
        int d = h * 64 + nt * 8 + 2 * tx;
        *(float2*)&g_O[(b * SEQ + srow) * CH + d] =
            make_float2(oacc[nt][0] * inv_lo, oacc[nt][1] * inv_lo);
        *(float2*)&g_O[(b * SEQ + srow + 8) * CH + d] =
            make_float2(oacc[nt][2] * inv_hi, oacc[nt][3] * inv_hi);
    }
}

// ============== kernel 3: proj GEMM + bias + residual + transpose ==========
// out[b,c,s] = sum_k O[b,s,k]*wp[k,c] + bp[c] + x[b,c,s]. M=16384,N=512,K=512
#define PASTR 36    // A [m][k]: frag bank = 4*g+tx, conflict-free
#define PBSTR 136
__global__ __launch_bounds__(256) void proj_kernel(const float* __restrict__ wp,
                                                   const float* __restrict__ bp,
                                                   const float* __restrict__ x,
                                                   float* __restrict__ out) {
    __shared__ unsigned As[128 * PASTR];  // [m][k]
    __shared__ unsigned Bs[32 * PBSTR];   // [k][n]

    const int m0 = blockIdx.x * 128, n0 = blockIdx.y * 128;
    const int b  = m0 >> 10, s0 = m0 & 1023;
    const int tid = threadIdx.x, lane = tid & 31, wid = tid >> 5;
    const int g = lane >> 2, tx = lane & 3;
    const int wm = (wid & 3) * 32, wn = (wid >> 2) * 64;

    const float* Ob = g_O + (b * SEQ + s0) * CH;

    float acc[2][8][4];
#pragma unroll
    for (int mt = 0; mt < 2; mt++)
#pragma unroll
        for (int nt = 0; nt < 8; nt++)
#pragma unroll
            for (int i = 0; i < 4; i++) acc[mt][nt][i] = 0.f;

    for (int k0 = 0; k0 < CH; k0 += 32) {
#pragma unroll
        for (int t = 0; t < 4; t++) {    // A tile 128m x 32k, k contiguous
            int f = tid * 4 + t * 1024;
            int mm = f >> 5, kk = f & 31;
            float4 v = *(const float4*)&Ob[mm * CH + k0 + kk];
            uint4 u = make_uint4(f2tf(v.x), f2tf(v.y), f2tf(v.z), f2tf(v.w));
            *(uint4*)&As[mm * PASTR + kk] = u;
        }
#pragma unroll
        for (int t = 0; t < 4; t++) {    // B tile 32k x 128n
            int f = tid * 4 + t * 1024;
            int kk = f >> 7, nn = f & 127;
            float4 v = *(const float4*)&wp[(k0 + kk) * CH + n0 + nn];
            uint4 u = make_uint4(f2tf(v.x), f2tf(v.y), f2tf(v.z), f2tf(v.w));
            *(uint4*)&Bs[kk * PBSTR + nn] = u;
        }
        __syncthreads();
#pragma unroll
        for (int ks = 0; ks < 4; ks++) {
            const int kb = ks * 8;
            unsigned af[2][4];
#pragma unroll
            for (int mt = 0; mt < 2; mt++) {
                int mrow = wm + mt * 16 + g;
                af[mt][0] = As[mrow * PASTR + kb + tx];
                af[mt][1] = As[(mrow + 8) * PASTR + kb + tx];
                af[mt][2] = As[mrow * PASTR + kb + tx + 4];
                af[mt][3] = As[(mrow + 8) * PASTR + kb + tx + 4];
            }
#pragma unroll
            for (int nt = 0; nt < 8; nt++) {
                unsigned bf[2];
                int nb = wn + nt * 8 + g;
                bf[0] = Bs[(kb + tx) * PBSTR + nb];
                bf[1] = Bs[(kb + tx + 4) * PBSTR + nb];
                mma8(acc[0][nt], af[0], bf, acc[0][nt]);
                mma8(acc[1][nt], af[1], bf, acc[1][nt]);
            }
        }
        __syncthreads();
    }

    // epilogue: out[b,c,s] with residual
#pragma unroll
    for (int nt = 0; nt < 8; nt++) {
        int c0 = n0 + wn + nt * 8 + 2 * tx;
        float bv0 = bp[c0], bv1 = bp[c0 + 1];
#pragma unroll
        for (int mt = 0; mt < 2; mt++) {
            int s = s0 + wm + mt * 16 + g;
            int i00 = b * CH * SEQ + c0 * SEQ + s;
            out[i00]           = acc[mt][nt][0] + bv0 + x[i00];
            out[i00 + SEQ]     = acc[mt][nt][1] + bv1 + x[i00 + SEQ];
            out[i00 + 8]       = acc[mt][nt][2] + bv0 + x[i00 + 8];
            out[i00 + SEQ + 8] = acc[mt][nt][3] + bv1 + x[i00 + SEQ + 8];
        }
    }
}

// ================================ launch ==================================
extern "C" void kernel_launch(void* const* d_in, const int* in_sizes, int n_in,
                              void* d_out, int out_size) {
    const float* x      = (const float*)d_in[0];
    const float* w_qkv  = (const float*)d_in[1];
    const float* b_qkv  = (const float*)d_in[2];
    const float* w_proj = (const float*)d_in[3];
    const float* b_proj = (const float*)d_in[4];
    float* out = (float*)d_out;

    const int smem_attn = (64 * KSTR * 2 + 128 * PSTR) * sizeof(float); // 75776
    cudaFuncSetAttribute(attn_kernel,
                         cudaFuncAttributeMaxDynamicSharedMemorySize, smem_attn);

    qkv_kernel<<<dim3(BATCH * SEQ / 128, N3 / 128), 256>>>(x, w_qkv, b_qkv);
    attn_kernel<<<dim3(SEQ / 128, BATCH * NH), 256, smem_attn>>>();
    proj_kernel<<<dim3(BATCH * SEQ / 128, CH / 128), 256>>>(w_proj, b_proj, x, out);
}

// round 3
// speedup vs baseline: 8.4954x; 2.5872x over previous
#include <cuda_runtime.h>
#include <cuda_bf16.h>

#define BATCH 16
#define CH    512
#define SEQ   1024
#define NH    8
#define DK    64
#define N3    1536
#define QSCALE 0.1803368801111244f   // 0.125 * log2(e)

typedef __nv_bfloat16 bf16;

// ---------------- scratch (device globals: allocation-free) ----------------
__device__ bf16 g_X [BATCH * SEQ * CH];        // x transposed [b,s,c]
__device__ bf16 g_Wq[CH * N3];
__device__ bf16 g_Wp[CH * CH];
__device__ bf16 g_Q [BATCH * NH * SEQ * DK];   // [b,h,s,d], pre-scaled
__device__ bf16 g_K [BATCH * NH * SEQ * DK];
__device__ bf16 g_V [BATCH * NH * SEQ * DK];
__device__ bf16 g_O [BATCH * SEQ * CH];        // [b,s,c]

// ------------------------------- helpers ----------------------------------
__device__ __forceinline__ unsigned s2u(const void* p) {
    return (unsigned)__cvta_generic_to_shared(p);
}
__device__ __forceinline__ void cpa(unsigned dst, const void* src) {
    asm volatile("cp.async.cg.shared.global [%0], [%1], 16;\n" :: "r"(dst), "l"(src));
}
#define CP_COMMIT asm volatile("cp.async.commit_group;\n" ::: "memory")
#define CP_WAIT0  asm volatile("cp.async.wait_group 0;\n" ::: "memory")

__device__ __forceinline__ void ldmx4(unsigned* r, unsigned a) {
    asm volatile("ldmatrix.sync.aligned.m8n8.x4.shared.b16 {%0,%1,%2,%3}, [%4];"
                 : "=r"(r[0]), "=r"(r[1]), "=r"(r[2]), "=r"(r[3]) : "r"(a));
}
__device__ __forceinline__ void ldmx4t(unsigned* r, unsigned a) {
    asm volatile("ldmatrix.sync.aligned.m8n8.x4.trans.shared.b16 {%0,%1,%2,%3}, [%4];"
                 : "=r"(r[0]), "=r"(r[1]), "=r"(r[2]), "=r"(r[3]) : "r"(a));
}
__device__ __forceinline__ void mma16(float* d, const unsigned* a,
                                      unsigned b0, unsigned b1, const float* c) {
    asm volatile(
        "mma.sync.aligned.m16n8k16.row.col.f32.bf16.bf16.f32 "
        "{%0,%1,%2,%3}, {%4,%5,%6,%7}, {%8,%9}, {%10,%11,%12,%13};"
        : "=f"(d[0]), "=f"(d[1]), "=f"(d[2]), "=f"(d[3])
        : "r"(a[0]), "r"(a[1]), "r"(a[2]), "r"(a[3]), "r"(b0), "r"(b1),
          "f"(c[0]), "f"(c[1]), "f"(c[2]), "f"(c[3]));
}
__device__ __forceinline__ unsigned packbf(float lo, float hi) {
    unsigned r;
    asm("cvt.rn.bf16x2.f32 %0, %1, %2;" : "=r"(r) : "f"(hi), "f"(lo));
    return r;
}

// ========================= pre-pass kernels ===============================
__global__ void xpose_kernel(const float* __restrict__ x) {
    __shared__ float t[32][33];
    const int b = blockIdx.z, c0 = blockIdx.y * 32, s0 = blockIdx.x * 32;
    const int tx = threadIdx.x, ty = threadIdx.y;
#pragma unroll
    for (int i = 0; i < 4; i++)
        t[ty + 8 * i][tx] = x[(b * CH + c0 + ty + 8 * i) * SEQ + s0 + tx];
    __syncthreads();
#pragma unroll
    for (int i = 0; i < 4; i++)
        g_X[(b * SEQ + s0 + ty + 8 * i) * CH + c0 + tx] =
            __float2bfloat16(t[tx][ty + 8 * i]);
}

__global__ void conv_kernel(const float* __restrict__ src, bf16* dst, int n) {
    for (int i = blockIdx.x * 256 + threadIdx.x; i < n; i += gridDim.x * 256)
        dst[i] = __float2bfloat16(src[i]);
}

// ======================= kernel 1: QKV GEMM + scatter ======================
// A = g_X[b] [m=s][k=c], B = g_Wq [k][n]. CTA 128x128, ktile 32, 8 warps.
#define GASTR 40    // A smem row stride (bf16)
#define GBSTR 136   // B smem row stride
__global__ __launch_bounds__(256) void qkv_kernel(const float* __restrict__ bias) {
    __shared__ bf16 As[2][128 * GASTR];
    __shared__ bf16 Bs[2][32 * GBSTR];

    const int m0 = blockIdx.x * 128, n0 = blockIdx.y * 128;
    const int b = m0 >> 10, s0 = m0 & 1023;
    const int tid = threadIdx.x, lane = tid & 31, wid = tid >> 5;
    const int tq = lane >> 2, tr = lane & 3;
    const int wm = (wid & 3) * 32, wn = (wid >> 2) * 64;

    const bf16* Asrc = g_X + (b * SEQ + s0) * CH;
    const bf16* Bsrc = g_Wq + n0;

    float acc[2][8][4];
#pragma unroll
    for (int mt = 0; mt < 2; mt++)
#pragma unroll
        for (int nt = 0; nt < 8; nt++)
#pragma unroll
            for (int i = 0; i < 4; i++) acc[mt][nt][i] = 0.f;

    unsigned aB[2] = { s2u(As[0]), s2u(As[1]) };
    unsigned bB[2] = { s2u(Bs[0]), s2u(Bs[1]) };

    // issue tile 0
#pragma unroll
    for (int i = 0; i < 2; i++) {
        int c = tid + i * 256;
        int r = c >> 2, ko = (c & 3) * 8;
        cpa(aB[0] + (r * GASTR + ko) * 2, Asrc + r * CH + ko);
        int rb = c >> 4, no = (c & 15) * 8;
        cpa(bB[0] + (rb * GBSTR + no) * 2, Bsrc + rb * N3 + no);
    }
    CP_COMMIT;

    for (int kt = 0; kt < 16; kt++) {
        CP_WAIT0;
        __syncthreads();
        if (kt < 15) {
            int k0 = (kt + 1) * 32, nb = (kt + 1) & 1;
#pragma unroll
            for (int i = 0; i < 2; i++) {
                int c = tid + i * 256;
                int r = c >> 2, ko = (c & 3) * 8;
                cpa(aB[nb] + (r * GASTR + ko) * 2, Asrc + r * CH + k0 + ko);
                int rb = c >> 4, no = (c & 15) * 8;
                cpa(bB[nb] + (rb * GBSTR + no) * 2, Bsrc + (k0 + rb) * N3 + no);
            }
            CP_COMMIT;
        }
        unsigned ab = aB[kt & 1], bb = bB[kt & 1];
#pragma unroll
        for (int ks = 0; ks < 2; ks++) {
            unsigned af[2][4];
#pragma unroll
            for (int mt = 0; mt < 2; mt++)
                ldmx4(af[mt], ab + (((wm + mt * 16 + (lane & 15)) * GASTR)
                                    + ks * 16 + 8 * (lane >> 4)) * 2);
#pragma unroll
            for (int ng = 0; ng < 4; ng++) {
                unsigned t[4];
                int row = ks * 16 + (lane & 7) + 8 * ((lane >> 3) & 1);
                int col = wn + ng * 16 + 8 * (lane >> 4);
                ldmx4t(t, bb + (row * GBSTR + col) * 2);
                mma16(acc[0][2 * ng],     af[0], t[0], t[1], acc[0][2 * ng]);
                mma16(acc[0][2 * ng + 1], af[0], t[2], t[3], acc[0][2 * ng + 1]);
                mma16(acc[1][2 * ng],     af[1], t[0], t[1], acc[1][2 * ng]);
                mma16(acc[1][2 * ng + 1], af[1], t[2], t[3], acc[1][2 * ng + 1]);
            }
        }
    }

    // epilogue: bias, (Q pre-scale), scatter bf16
#pragma unroll
    for (int nt = 0; nt < 8; nt++) {
        int n = n0 + wn + nt * 8 + 2 * tr;
        int h = n / 192, r = n - h * 192;
        bf16* dst; int d; float sc = 1.f;
        if (r < 64)       { dst = g_Q; d = r;       sc = QSCALE; }
        else if (r < 128) { dst = g_K; d = r - 64;  }
        else              { dst = g_V; d = r - 128; }
        float bv0 = bias[n], bv1 = bias[n + 1];
        int rowbase = (b * NH + h) * SEQ;
#pragma unroll
        for (int mt = 0; mt < 2; mt++) {
            int s = s0 + wm + mt * 16 + tq;
            *(unsigned*)&dst[(rowbase + s) * DK + d] =
                packbf((acc[mt][nt][0] + bv0) * sc, (acc[mt][nt][1] + bv1) * sc);
            *(unsigned*)&dst[(rowbase + s + 8) * DK + d] =
                packbf((acc[mt][nt][2] + bv0) * sc, (acc[mt][nt][3] + bv1) * sc);
        }
    }
}

// ==================== kernel 2: flash attention (bf16) =====================
// CTA = 128 q-rows x (b,h). 8 warps x m16. j-tiles 64, P in registers.
#define TSTR 72
__global__ __launch_bounds__(256) void attn_kernel() {
    extern __shared__ bf16 sm[];
    bf16* Qs  = sm;                       // 128*TSTR
    bf16* Ks0 = Qs + 128 * TSTR;          // 2 x 64*TSTR
    bf16* Vs0 = Ks0 + 2 * 64 * TSTR;      // 2 x 64*TSTR

    const int i0 = blockIdx.x * 128;
    const int bh = blockIdx.y;
    const int tid = threadIdx.x, lane = tid & 31, wid = tid >> 5;
    const int tq = lane >> 2, tr = lane & 3;

    const bf16* Qg = g_Q + (bh * SEQ + i0) * DK;
    const bf16* Kg0 = g_K + bh * SEQ * DK;
    const bf16* Vg0 = g_V + bh * SEQ * DK;

    unsigned kB[2] = { s2u(Ks0), s2u(Ks0 + 64 * TSTR) };
    unsigned vB[2] = { s2u(Vs0), s2u(Vs0 + 64 * TSTR) };

    // stage Q tile + issue K/V tile 0
#pragma unroll
    for (int i = 0; i < 4; i++) {
        int c = tid + i * 256;
        int r = c >> 3, co = (c & 7) * 8;
        *(uint4*)&Qs[r * TSTR + co] = *(const uint4*)&Qg[r * DK + co];
    }
#pragma unroll
    for (int i = 0; i < 2; i++) {
        int c = tid + i * 256;
        int r = c >> 3, co = (c & 7) * 8;
        cpa(kB[0] + (r * TSTR + co) * 2, Kg0 + r * DK + co);
        cpa(vB[0] + (r * TSTR + co) * 2, Vg0 + r * DK + co);
    }
    CP_COMMIT;
    __syncthreads();

    // Q fragments (pre-scaled by QSCALE at QKV epilogue)
    unsigned qa[4][4];
    unsigned qbase = s2u(Qs);
#pragma unroll
    for (int ks = 0; ks < 4; ks++)
        ldmx4(qa[ks], qbase + (((wid * 16 + (lane & 15)) * TSTR)
                               + ks * 16 + 8 * (lane >> 4)) * 2);

    float oa[8][4];
#pragma unroll
    for (int nt = 0; nt < 8; nt++)
#pragma unroll
        for (int i = 0; i < 4; i++) oa[nt][i] = 0.f;
    float m_lo = -1e30f, m_hi = -1e30f, l_lo = 0.f, l_hi = 0.f;

    for (int jt = 0; jt < 16; jt++) {
        CP_WAIT0;
        __syncthreads();
        if (jt < 15) {
            int nb = (jt + 1) & 1;
            const bf16* Kg = Kg0 + (jt + 1) * 64 * DK;
            const bf16* Vg = Vg0 + (jt + 1) * 64 * DK;
#pragma unroll
            for (int i = 0; i < 2; i++) {
                int c = tid + i * 256;
                int r = c >> 3, co = (c & 7) * 8;
                cpa(kB[nb] + (r * TSTR + co) * 2, Kg + r * DK + co);
                cpa(vB[nb] + (r * TSTR + co) * 2, Vg + r * DK + co);
            }
            CP_COMMIT;
        }
        unsigned kb = kB[jt & 1], vb = vB[jt & 1];

        // S = Q K^T (16 x 64)
        float sa[8][4];
#pragma unroll
        for (int nt = 0; nt < 8; nt++)
#pragma unroll
            for (int i = 0; i < 4; i++) sa[nt][i] = 0.f;
#pragma unroll
        for (int ks = 0; ks < 4; ks++) {
#pragma unroll
            for (int ng = 0; ng < 4; ng++) {
                unsigned t[4];
                int row = ng * 16 + (lane & 15);
                int col = ks * 16 + 8 * (lane >> 4);
                ldmx4(t, kb + (row * TSTR + col) * 2);
                mma16(sa[2 * ng],     qa[ks], t[0], t[2], sa[2 * ng]);
                mma16(sa[2 * ng + 1], qa[ks], t[1], t[3], sa[2 * ng + 1]);
            }
        }

        // online softmax, exp2 domain; rows tq and tq+8, group = 4 lanes
        float mx_lo = -1e30f, mx_hi = -1e30f;
#pragma unroll
        for (int nt = 0; nt < 8; nt++) {
            mx_lo = fmaxf(mx_lo, fmaxf(sa[nt][0], sa[nt][1]));
            mx_hi = fmaxf(mx_hi, fmaxf(sa[nt][2], sa[nt][3]));
        }
#pragma unroll
        for (int off = 1; off <= 2; off <<= 1) {
            mx_lo = fmaxf(mx_lo, __shfl_xor_sync(0xffffffffu, mx_lo, off));
            mx_hi = fmaxf(mx_hi, __shfl_xor_sync(0xffffffffu, mx_hi, off));
        }
        float mn_lo = fmaxf(m_lo, mx_lo), mn_hi = fmaxf(m_hi, mx_hi);
        float corr_lo = exp2f(m_lo - mn_lo), corr_hi = exp2f(m_hi - mn_hi);
        float rs_lo = 0.f, rs_hi = 0.f;
#pragma unroll
        for (int nt = 0; nt < 8; nt++) {
            sa[nt][0] = exp2f(sa[nt][0] - mn_lo);
            sa[nt][1] = exp2f(sa[nt][1] - mn_lo);
            sa[nt][2] = exp2f(sa[nt][2] - mn_hi);
            sa[nt][3] = exp2f(sa[nt][3] - mn_hi);
            rs_lo += sa[nt][0] + sa[nt][1];
            rs_hi += sa[nt][2] + sa[nt][3];
        }
#pragma unroll
        for (int off = 1; off <= 2; off <<= 1) {
            rs_lo += __shfl_xor_sync(0xffffffffu, rs_lo, off);
            rs_hi += __shfl_xor_sync(0xffffffffu, rs_hi, off);
        }
        l_lo = l_lo * corr_lo + rs_lo;  m_lo = mn_lo;
        l_hi = l_hi * corr_hi + rs_hi;  m_hi = mn_hi;
#pragma unroll
        for (int nt = 0; nt < 8; nt++) {
            oa[nt][0] *= corr_lo; oa[nt][1] *= corr_lo;
            oa[nt][2] *= corr_hi; oa[nt][3] *= corr_hi;
        }

        // P: C-frag -> A-frag (registers only)
        unsigned pa[4][4];
#pragma unroll
        for (int ks = 0; ks < 4; ks++) {
            pa[ks][0] = packbf(sa[2 * ks][0],     sa[2 * ks][1]);
            pa[ks][1] = packbf(sa[2 * ks][2],     sa[2 * ks][3]);
            pa[ks][2] = packbf(sa[2 * ks + 1][0], sa[2 * ks + 1][1]);
            pa[ks][3] = packbf(sa[2 * ks + 1][2], sa[2 * ks + 1][3]);
        }

        // O += P V
#pragma unroll
        for (int ks = 0; ks < 4; ks++) {
#pragma unroll
            for (int ng = 0; ng < 4; ng++) {
                unsigned t[4];
                int row = ks * 16 + (lane & 7) + 8 * ((lane >> 3) & 1);
                int col = ng * 16 + 8 * (lane >> 4);
                ldmx4t(t, vb + (row * TSTR + col) * 2);
                mma16(oa[2 * ng],     pa[ks], t[0], t[1], oa[2 * ng]);
                mma16(oa[2 * ng + 1], pa[ks], t[2], t[3], oa[2 * ng + 1]);
            }
        }
    }

    // epilogue -> g_O bf16 [b,s,c]
    float inv_lo = 1.f / l_lo, inv_hi = 1.f / l_hi;
    const int b = bh >> 3, h = bh & 7;
    const int s = i0 + wid * 16 + tq;
#pragma unroll
    for (int nt = 0; nt < 8; nt++) {
        int d = h * 64 + nt * 8 + 2 * tr;
        *(unsigned*)&g_O[(b * SEQ + s) * CH + d] =
            packbf(oa[nt][0] * inv_lo, oa[nt][1] * inv_lo);
        *(unsigned*)&g_O[(b * SEQ + s + 8) * CH + d] =
            packbf(oa[nt][2] * inv_hi, oa[nt][3] * inv_hi);
    }
}

// ============== kernel 3: proj GEMM + bias + residual + transpose ==========
__global__ __launch_bounds__(256) void proj_kernel(const float* __restrict__ bp,
                                                   const float* __restrict__ x,
                                                   float* __restrict__ out) {
    __shared__ bf16 As[2][128 * GASTR];
    __shared__ bf16 Bs[2][32 * GBSTR];

    const int m0 = blockIdx.x * 128, n0 = blockIdx.y * 128;
    const int b = m0 >> 10, s0 = m0 & 1023;
    const int tid = threadIdx.x, lane = tid & 31, wid = tid >> 5;
    const int tq = lane >> 2, tr = lane & 3;
    const int wm = (wid & 3) * 32, wn = (wid >> 2) * 64;

    const bf16* Asrc = g_O + (b * SEQ + s0) * CH;
    const bf16* Bsrc = g_Wp + n0;

    float acc[2][8][4];
#pragma unroll
    for (int mt = 0; mt < 2; mt++)
#pragma unroll
        for (int nt = 0; nt < 8; nt++)
#pragma unroll
            for (int i = 0; i < 4; i++) acc[mt][nt][i] = 0.f;

    unsigned aB[2] = { s2u(As[0]), s2u(As[1]) };
    unsigned bB[2] = { s2u(Bs[0]), s2u(Bs[1]) };

#pragma unroll
    for (int i = 0; i < 2; i++) {
        int c = tid + i * 256;
        int r = c >> 2, ko = (c & 3) * 8;
        cpa(aB[0] + (r * GASTR + ko) * 2, Asrc + r * CH + ko);
        int rb = c >> 4, no = (c & 15) * 8;
        cpa(bB[0] + (rb * GBSTR + no) * 2, Bsrc + rb * CH + no);
    }
    CP_COMMIT;

    for (int kt = 0; kt < 16; kt++) {
        CP_WAIT0;
        __syncthreads();
        if (kt < 15) {
            int k0 = (kt + 1) * 32, nb = (kt + 1) & 1;
#pragma unroll
            for (int i = 0; i < 2; i++) {
                int c = tid + i * 256;
                int r = c >> 2, ko = (c & 3) * 8;
                cpa(aB[nb] + (r * GASTR + ko) * 2, Asrc + r * CH + k0 + ko);
                int rb = c >> 4, no = (c & 15) * 8;
                cpa(bB[nb] + (rb * GBSTR + no) * 2, Bsrc + (k0 + rb) * CH + no);
            }
            CP_COMMIT;
        }
        unsigned ab = aB[kt & 1], bb = bB[kt & 1];
#pragma unroll
        for (int ks = 0; ks < 2; ks++) {
            unsigned af[2][4];
#pragma unroll
            for (int mt = 0; mt < 2; mt++)
                ldmx4(af[mt], ab + (((wm + mt * 16 + (lane & 15)) * GASTR)
                                    + ks * 16 + 8 * (lane >> 4)) * 2);
#pragma unroll
            for (int ng = 0; ng < 4; ng++) {
                unsigned t[4];
                int row = ks * 16 + (lane & 7) + 8 * ((lane >> 3) & 1);
                int col = wn + ng * 16 + 8 * (lane >> 4);
                ldmx4t(t, bb + (row * GBSTR + col) * 2);
                mma16(acc[0][2 * ng],     af[0], t[0], t[1], acc[0][2 * ng]);
                mma16(acc[0][2 * ng + 1], af[0], t[2], t[3], acc[0][2 * ng + 1]);
                mma16(acc[1][2 * ng],     af[1], t[0], t[1], acc[1][2 * ng]);
                mma16(acc[1][2 * ng + 1], af[1], t[2], t[3], acc[1][2 * ng + 1]);
            }
        }
    }

    // epilogue: out[b,c,s] = acc + bias + x (exact fp32 residual)
#pragma unroll
    for (int nt = 0; nt < 8; nt++) {
        int c0 = n0 + wn + nt * 8 + 2 * tr;
        float bv0 = bp[c0], bv1 = bp[c0 + 1];
#pragma unroll
        for (int mt = 0; mt < 2; mt++) {
            int s = s0 + wm + mt * 16 + tq;
            int i00 = b * CH * SEQ + c0 * SEQ + s;
            out[i00]           = acc[mt][nt][0] + bv0 + x[i00];
            out[i00 + SEQ]     = acc[mt][nt][1] + bv1 + x[i00 + SEQ];
            out[i00 + 8]       = acc[mt][nt][2] + bv0 + x[i00 + 8];
            out[i00 + SEQ + 8] = acc[mt][nt][3] + bv1 + x[i00 + SEQ + 8];
        }
    }
}

// ================================ launch ==================================
extern "C" void kernel_launch(void* const* d_in, const int* in_sizes, int n_in,
                              void* d_out, int out_size) {
    const float* x      = (const float*)d_in[0];
    const float* w_qkv  = (const float*)d_in[1];
    const float* b_qkv  = (const float*)d_in[2];
    const float* w_proj = (const float*)d_in[3];
    const float* b_proj = (const float*)d_in[4];
    float* out = (float*)d_out;

    bf16 *wq_d, *wp_d;
    cudaGetSymbolAddress((void**)&wq_d, g_Wq);
    cudaGetSymbolAddress((void**)&wp_d, g_Wp);

    const int smem_attn = (128 * TSTR + 4 * 64 * TSTR) * sizeof(bf16); // 55296
    cudaFuncSetAttribute(attn_kernel,
                         cudaFuncAttributeMaxDynamicSharedMemorySize, smem_attn);

    xpose_kernel<<<dim3(SEQ / 32, CH / 32, BATCH), dim3(32, 8)>>>(x);
    conv_kernel<<<768, 256>>>(w_qkv, wq_d, CH * N3);
    conv_kernel<<<256, 256>>>(w_proj, wp_d, CH * CH);
    qkv_kernel<<<dim3(BATCH * SEQ / 128, N3 / 128), 256>>>(b_qkv);
    attn_kernel<<<dim3(SEQ / 128, BATCH * NH), 256, smem_attn>>>();
    proj_kernel<<<dim3(BATCH * SEQ / 128, CH / 128), 256>>>(b_proj, x, out);
}